// round 16
// baseline (speedup 1.0000x reference)
#include <cuda_runtime.h>
#include <cuda_fp16.h>
#include <cstdint>

// ============================================================================
// out[M,N] = x[M,K] @ w_bin[N,K]^T + bias[N]
//   w_bin = (w < mean-std || w > mean+std) ? w : sign(w)   (std: ddof=1)
// Shapes: M=16384, K=4096, N=4096 fp32.
// Engine: fp16 convert + mma.sync.m16n8k16 pipelined GEMM (base sm_103 ISA).
// R16: R15 + cp.async issue smoothing — 16 cps split into four 4-op quarters
//      interleaved between MMA bursts; A-quarter at kt top gives ~2-kt fill
//      lead so WAITG is nearly free. Same barriers/commits as R15 (proven).
// ============================================================================

#define MAXM 16384
#define MAXN 4096
#define MAXK 4096

__device__ __half g_Xh[(size_t)MAXM * MAXK];   // 128 MiB scratch
__device__ __half g_Wb[(size_t)MAXN * MAXK];   // 32 MiB scratch
__device__ double g_part[2048];

// ---------------------------------------------------------------- stats ----
__global__ void stats1_kernel(const float* __restrict__ w, int n) {
    __shared__ double ss[256], sq[256];
    double s = 0.0, q = 0.0;
    for (int i = blockIdx.x * blockDim.x + threadIdx.x; i < n; i += gridDim.x * blockDim.x) {
        double v = (double)w[i];
        s += v; q += v * v;
    }
    ss[threadIdx.x] = s; sq[threadIdx.x] = q;
    __syncthreads();
    for (int o = 128; o > 0; o >>= 1) {
        if (threadIdx.x < o) { ss[threadIdx.x] += ss[threadIdx.x + o]; sq[threadIdx.x] += sq[threadIdx.x + o]; }
        __syncthreads();
    }
    if (threadIdx.x == 0) { g_part[blockIdx.x * 2] = ss[0]; g_part[blockIdx.x * 2 + 1] = sq[0]; }
}

__device__ __forceinline__ float binv(float w, float lo, float hi) {
    if (w < lo || w > hi) return w;
    return (w > 0.f) ? 1.f : ((w < 0.f) ? -1.f : 0.f);
}

// binarize + final threshold reduce fused (each block redundantly reduces the
// 1024 partials — deterministic, a few us total).
__global__ void binarize_kernel(const float* __restrict__ w, int n4, int n) {
    __shared__ double ss[256], sq[256];
    __shared__ float thr[2];
    double s = 0.0, q = 0.0;
    for (int i = threadIdx.x; i < 1024; i += 256) { s += g_part[2 * i]; q += g_part[2 * i + 1]; }
    ss[threadIdx.x] = s; sq[threadIdx.x] = q;
    __syncthreads();
    for (int o = 128; o > 0; o >>= 1) {
        if (threadIdx.x < o) { ss[threadIdx.x] += ss[threadIdx.x + o]; sq[threadIdx.x] += sq[threadIdx.x + o]; }
        __syncthreads();
    }
    if (threadIdx.x == 0) {
        double mean = ss[0] / (double)n;
        double var  = (sq[0] - ss[0] * ss[0] / (double)n) / (double)(n - 1);
        double sd = sqrt(var);
        thr[0] = (float)(mean - sd);
        thr[1] = (float)(mean + sd);
    }
    __syncthreads();
    float lo = thr[0], hi = thr[1];
    const float4* w4 = (const float4*)w;
    __half2* o2 = (__half2*)g_Wb;
    for (int i = blockIdx.x * blockDim.x + threadIdx.x; i < n4; i += gridDim.x * blockDim.x) {
        float4 v = w4[i];
        o2[2 * i]     = __floats2half2_rn(binv(v.x, lo, hi), binv(v.y, lo, hi));
        o2[2 * i + 1] = __floats2half2_rn(binv(v.z, lo, hi), binv(v.w, lo, hi));
    }
}

__global__ void xconv_kernel(const float* __restrict__ x, int n4) {
    const float4* x4 = (const float4*)x;
    __half2* o2 = (__half2*)g_Xh;
    for (int i = blockIdx.x * blockDim.x + threadIdx.x; i < n4; i += gridDim.x * blockDim.x) {
        float4 v = x4[i];
        o2[2 * i]     = __floats2half2_rn(v.x, v.y);
        o2[2 * i + 1] = __floats2half2_rn(v.z, v.w);
    }
}

// ---------------------------------------------------------------- GEMM -----
// CTA tile 128x128, BK=64, 3-stage cp.async, 128 threads (4 warps 2x2),
// warp tile 64x64, cross-kt fragment pipelining, 2 CTAs/SM.
// Smem rows 144B: 16B-aligned cp.async dsts, ldmatrix phase-conflict-free.

#define BM 128
#define BN 128
#define BK 64
#define ROWB 144
#define STAGE_A (BM * ROWB)           // 18432
#define STAGE_B (BN * ROWB)           // 18432
#define STAGE   (STAGE_A + STAGE_B)   // 36864
#define NSTG 3
#define GEMM_SMEM (NSTG * STAGE)      // 110592 (x2 CTAs = 221KB/SM)

__device__ __forceinline__ uint32_t smem_u32(const void* p) {
    uint32_t a;
    asm("{ .reg .u64 t; cvta.to.shared.u64 t, %1; cvt.u32.u64 %0, t; }" : "=r"(a) : "l"(p));
    return a;
}
__device__ __forceinline__ void cp16(uint32_t s, const void* g) {
    asm volatile("cp.async.cg.shared.global [%0], [%1], 16;" :: "r"(s), "l"(g));
}
#define CP_COMMIT() asm volatile("cp.async.commit_group;" ::: "memory")
#define CP_WAITG(n) asm volatile("cp.async.wait_group %0;" :: "n"(n) : "memory")

#define LDSM4(r0, r1, r2, r3, addr) \
    asm volatile("ldmatrix.sync.aligned.m8n8.x4.shared.b16 {%0,%1,%2,%3}, [%4];" \
        : "=r"(r0), "=r"(r1), "=r"(r2), "=r"(r3) : "r"(addr))

__device__ __forceinline__ void mma16816(float* d, const uint32_t* a, const uint32_t* b) {
    asm volatile(
        "mma.sync.aligned.m16n8k16.row.col.f32.f16.f16.f32 "
        "{%0,%1,%2,%3}, {%4,%5,%6,%7}, {%8,%9}, {%0,%1,%2,%3};"
        : "+f"(d[0]), "+f"(d[1]), "+f"(d[2]), "+f"(d[3])
        : "r"(a[0]), "r"(a[1]), "r"(a[2]), "r"(a[3]), "r"(b[0]), "r"(b[1]));
}

// Quarter-stage issues (4 cp16/thread each). A = rows 0..127 of x-tile slice,
// B = rows of w-tile slice; jq selects which 4-of-8 chunk group.
__device__ __forceinline__ void issue_A_q(
    uint32_t sb, int stage, const __half* __restrict__ gA, int kt, int tid, int K, int jq)
{
    uint32_t sA = sb + stage * STAGE;
    const __half* ga = gA + (size_t)kt * BK;
    #pragma unroll
    for (int j = jq * 4; j < jq * 4 + 4; j++) {
        int cid = tid + j * 128;
        int r = cid >> 3, c = cid & 7;
        cp16(sA + r * ROWB + c * 16, ga + (size_t)r * K + c * 8);
    }
}
__device__ __forceinline__ void issue_B_q(
    uint32_t sb, int stage, const __half* __restrict__ gB, int kt, int tid, int K, int jq)
{
    uint32_t sB = sb + stage * STAGE + STAGE_A;
    const __half* gb = gB + (size_t)kt * BK;
    #pragma unroll
    for (int j = jq * 4; j < jq * 4 + 4; j++) {
        int cid = tid + j * 128;
        int r = cid >> 3, c = cid & 7;
        cp16(sB + r * ROWB + c * 16, gb + (size_t)r * K + c * 8);
    }
}

// Fragment loads for one k16 step.
#define LOAD_A_FRAGS(dst, base, kc) do { \
    _Pragma("unroll") \
    for (int mt = 0; mt < 4; mt++) { \
        uint32_t ad = (base) + (aRow + mt * 16) * ROWB + ((aCol + (kc)) * 2); \
        LDSM4((dst)[mt][0], (dst)[mt][1], (dst)[mt][2], (dst)[mt][3], ad); \
    } } while (0)

#define LOAD_B_FRAGS(dst, base, kc) do { \
    _Pragma("unroll") \
    for (int p = 0; p < 4; p++) { \
        uint32_t bd = (base) + (bRowBase + p * 16) * ROWB + ((bCol + (kc)) * 2); \
        uint32_t r0, r1, r2, r3; \
        LDSM4(r0, r1, r2, r3, bd); \
        (dst)[2 * p][0] = r0; (dst)[2 * p][1] = r1; \
        (dst)[2 * p + 1][0] = r2; (dst)[2 * p + 1][1] = r3; \
    } } while (0)

#define MMA_BURST(af, bf) do { \
    _Pragma("unroll") \
    for (int mt = 0; mt < 4; mt++) \
        _Pragma("unroll") \
        for (int nt = 0; nt < 8; nt++) \
            mma16816(acc[mt][nt], (af)[mt], (bf)[nt]); \
    } while (0)

__global__ void __launch_bounds__(128, 2)
gemm_kernel(float* __restrict__ out, const float* __restrict__ bias,
            const __half* __restrict__ A, const __half* __restrict__ B,
            int M, int N, int K)
{
    extern __shared__ char smem[];
    uint32_t sb = smem_u32(smem);

    int tid = threadIdx.x;
    int wid = tid >> 5, L = tid & 31;
    int warpM = wid >> 1, warpN = wid & 1;         // 2(M) x 2(N)

    int NT = N / BN;                               // 32
    int ntile = blockIdx.x % NT;                   // fast N => W stays L2-hot
    int mtile = blockIdx.x / NT;

    const __half* gA = A + (size_t)(mtile * BM) * K;
    const __half* gB = B + (size_t)(ntile * BN) * K;
    int KT = K / BK;                               // 64

    float acc[4][8][4];
    #pragma unroll
    for (int i = 0; i < 4; i++)
        #pragma unroll
        for (int j = 0; j < 8; j++)
            #pragma unroll
            for (int q = 0; q < 4; q++) acc[i][j][q] = 0.f;

    // prologue: fill stages 0,1
    issue_A_q(sb, 0, gA, 0, tid, K, 0); issue_A_q(sb, 0, gA, 0, tid, K, 1);
    issue_B_q(sb, 0, gB, 0, tid, K, 0); issue_B_q(sb, 0, gB, 0, tid, K, 1);
    CP_COMMIT();
    issue_A_q(sb, 1, gA, 1, tid, K, 0); issue_A_q(sb, 1, gA, 1, tid, K, 1);
    issue_B_q(sb, 1, gB, 1, tid, K, 0); issue_B_q(sb, 1, gB, 1, tid, K, 1);
    CP_COMMIT();

    // ldmatrix lane offsets (warp 64x64 mapping validated R6/R11-R15)
    int aRow = warpM * 64 + (L & 15);              // + mt*16
    int aCol = (L >> 4) << 3;                      // + ks*16
    int jb = L >> 3;
    int bRowBase = warpN * 64 + ((jb >> 1) << 3) + (L & 7);   // + p*16
    int bCol = (jb & 1) << 3;                      // + ks*16

    // F0 carries ks0 -> ks2 -> next-ks0 ; F1 carries ks1 -> ks3
    uint32_t aF[2][4][4], bF[2][8][2];

    // stage 0 resident (leave stage 1 pending), load kt0 ks0 fragments
    CP_WAITG(1);
    __syncthreads();
    LOAD_A_FRAGS(aF[0], sb, 0);
    LOAD_B_FRAGS(bF[0], sb + STAGE_A, 0);

    int st = 0;                                    // stage of current kt
    for (int kt = 0; kt < KT; kt++) {
        uint32_t sA = sb + st * STAGE;
        uint32_t sB = sA + STAGE_A;
        int st2 = st + 2; if (st2 >= NSTG) st2 -= NSTG;
        bool pf = (kt + 2 < KT);

        // quarter 1 of stage kt+2 at kt top: max fill lead (~2 kt).
        // Target stage (kt-1)%3 was fully read before the kt-1 barrier.
        if (pf) issue_A_q(sb, st2, gA, kt + 2, tid, K, 0);

        LOAD_A_FRAGS(aF[1], sA, 16);               // ks1 fragments
        LOAD_B_FRAGS(bF[1], sB, 16);

        MMA_BURST(aF[0], bF[0]);                   // ks0

        if (pf) issue_A_q(sb, st2, gA, kt + 2, tid, K, 1);

        LOAD_A_FRAGS(aF[0], sA, 32);               // ks2 fragments
        LOAD_B_FRAGS(bF[0], sB, 32);

        MMA_BURST(aF[1], bF[1]);                   // ks1

        if (pf) issue_B_q(sb, st2, gB, kt + 2, tid, K, 0);

        LOAD_A_FRAGS(aF[1], sA, 48);               // ks3 fragments (last st read)
        LOAD_B_FRAGS(bF[1], sB, 48);

        if (pf) issue_B_q(sb, st2, gB, kt + 2, tid, K, 1);
        CP_COMMIT();                               // one group per kt (tail-safe)

        MMA_BURST(aF[0], bF[0]);                   // ks2

        // single sync point per kt: stage kt+1 resident (only kt+2 pending);
        // all warps past all reads of stage st => next kt's issue is safe.
        CP_WAITG(1);
        __syncthreads();

        // cross-kt: ks0 fragments of kt+1 under the ks3 MMA shadow
        if (kt + 1 < KT) {
            int st1 = st + 1; if (st1 >= NSTG) st1 -= NSTG;
            uint32_t nA = sb + st1 * STAGE;
            LOAD_A_FRAGS(aF[0], nA, 0);
            LOAD_B_FRAGS(bF[0], nA + STAGE_A, 0);
        }

        MMA_BURST(aF[1], bF[1]);                   // ks3

        if (++st == NSTG) st = 0;
    }

    // ---------------- epilogue: fp32 stores (streaming) + bias ------------
    int rbase = mtile * BM + warpM * 64 + (L >> 2);
    int cbase = ntile * BN + warpN * 64 + (L & 3) * 2;

    float2 bv[8];
    #pragma unroll
    for (int nt = 0; nt < 8; nt++)
        bv[nt] = *(const float2*)(bias + cbase + nt * 8);

    #pragma unroll
    for (int mt = 0; mt < 4; mt++) {
        int r0 = rbase + mt * 16;
        #pragma unroll
        for (int nt = 0; nt < 8; nt++) {
            int c = cbase + nt * 8;
            float2 v0 = { acc[mt][nt][0] + bv[nt].x, acc[mt][nt][1] + bv[nt].y };
            float2 v1 = { acc[mt][nt][2] + bv[nt].x, acc[mt][nt][3] + bv[nt].y };
            __stcs((float2*)(out + (size_t)r0 * N + c), v0);
            __stcs((float2*)(out + (size_t)(r0 + 8) * N + c), v1);
        }
    }
}

// ---------------------------------------------------------------- host -----
extern "C" void kernel_launch(void* const* d_in, const int* in_sizes, int n_in,
                              void* d_out, int out_size)
{
    const float* x    = (const float*)d_in[0];
    const float* w    = (const float*)d_in[1];
    const float* bias = (const float*)d_in[2];
    float* out = (float*)d_out;

    int N  = in_sizes[2];
    int K  = in_sizes[1] / N;
    int M  = in_sizes[0] / K;
    int nw = in_sizes[1];
    int nx = in_sizes[0];

    // Order: gemm stays 4th kernel -> lands in the ncu capture slot.
    xconv_kernel<<<4096, 256>>>(x, nx / 4);
    stats1_kernel<<<1024, 256>>>(w, nw);
    binarize_kernel<<<2048, 256>>>(w, nw / 4, nw);

    void *pXh = nullptr, *pWb = nullptr;
    cudaGetSymbolAddress(&pXh, g_Xh);
    cudaGetSymbolAddress(&pWb, g_Wb);

    cudaFuncSetAttribute(gemm_kernel, cudaFuncAttributeMaxDynamicSharedMemorySize, GEMM_SMEM);

    int grid = (M / BM) * (N / BN);
    gemm_kernel<<<grid, 128, GEMM_SMEM>>>(out, bias, (const __half*)pXh,
                                          (const __half*)pWb, M, N, K);
}

// round 17
// speedup vs baseline: 1.0591x; 1.0591x over previous
#include <cuda_runtime.h>
#include <cuda_fp16.h>
#include <cstdint>

// ============================================================================
// out[M,N] = x[M,K] @ w_bin[N,K]^T + bias[N]
//   w_bin = (w < mean-std || w > mean+std) ? w : sign(w)   (std: ddof=1)
// Shapes: M=16384, K=4096, N=4096 fp32.
// Engine: fp16 convert + mma.sync.m16n8k16 pipelined GEMM (base sm_103 ISA).
// R17: mainloop __syncthreads/wait_group replaced by per-stage full/empty
//      mbarriers (cp.async.mbarrier.arrive.noinc) — warps decouple, drift ~1kt,
//      cover each other's stalls. Loop unrolled x3 so parities = j&1 (no
//      phase registers). Data schedule identical to R15 (best: 1296us, 83%).
// ============================================================================

#define MAXM 16384
#define MAXN 4096
#define MAXK 4096

__device__ __half g_Xh[(size_t)MAXM * MAXK];   // 128 MiB scratch
__device__ __half g_Wb[(size_t)MAXN * MAXK];   // 32 MiB scratch
__device__ double g_part[2048];

// ---------------------------------------------------------------- stats ----
__global__ void stats1_kernel(const float* __restrict__ w, int n) {
    __shared__ double ss[256], sq[256];
    double s = 0.0, q = 0.0;
    for (int i = blockIdx.x * blockDim.x + threadIdx.x; i < n; i += gridDim.x * blockDim.x) {
        double v = (double)w[i];
        s += v; q += v * v;
    }
    ss[threadIdx.x] = s; sq[threadIdx.x] = q;
    __syncthreads();
    for (int o = 128; o > 0; o >>= 1) {
        if (threadIdx.x < o) { ss[threadIdx.x] += ss[threadIdx.x + o]; sq[threadIdx.x] += sq[threadIdx.x + o]; }
        __syncthreads();
    }
    if (threadIdx.x == 0) { g_part[blockIdx.x * 2] = ss[0]; g_part[blockIdx.x * 2 + 1] = sq[0]; }
}

__device__ __forceinline__ float binv(float w, float lo, float hi) {
    if (w < lo || w > hi) return w;
    return (w > 0.f) ? 1.f : ((w < 0.f) ? -1.f : 0.f);
}

// binarize + final threshold reduce fused (each block redundantly reduces the
// 1024 partials — deterministic, a few us total).
__global__ void binarize_kernel(const float* __restrict__ w, int n4, int n) {
    __shared__ double ss[256], sq[256];
    __shared__ float thr[2];
    double s = 0.0, q = 0.0;
    for (int i = threadIdx.x; i < 1024; i += 256) { s += g_part[2 * i]; q += g_part[2 * i + 1]; }
    ss[threadIdx.x] = s; sq[threadIdx.x] = q;
    __syncthreads();
    for (int o = 128; o > 0; o >>= 1) {
        if (threadIdx.x < o) { ss[threadIdx.x] += ss[threadIdx.x + o]; sq[threadIdx.x] += sq[threadIdx.x + o]; }
        __syncthreads();
    }
    if (threadIdx.x == 0) {
        double mean = ss[0] / (double)n;
        double var  = (sq[0] - ss[0] * ss[0] / (double)n) / (double)(n - 1);
        double sd = sqrt(var);
        thr[0] = (float)(mean - sd);
        thr[1] = (float)(mean + sd);
    }
    __syncthreads();
    float lo = thr[0], hi = thr[1];
    const float4* w4 = (const float4*)w;
    __half2* o2 = (__half2*)g_Wb;
    for (int i = blockIdx.x * blockDim.x + threadIdx.x; i < n4; i += gridDim.x * blockDim.x) {
        float4 v = w4[i];
        o2[2 * i]     = __floats2half2_rn(binv(v.x, lo, hi), binv(v.y, lo, hi));
        o2[2 * i + 1] = __floats2half2_rn(binv(v.z, lo, hi), binv(v.w, lo, hi));
    }
}

__global__ void xconv_kernel(const float* __restrict__ x, int n4) {
    const float4* x4 = (const float4*)x;
    __half2* o2 = (__half2*)g_Xh;
    for (int i = blockIdx.x * blockDim.x + threadIdx.x; i < n4; i += gridDim.x * blockDim.x) {
        float4 v = x4[i];
        o2[2 * i]     = __floats2half2_rn(v.x, v.y);
        o2[2 * i + 1] = __floats2half2_rn(v.z, v.w);
    }
}

// ---------------------------------------------------------------- GEMM -----
// CTA tile 128x128, BK=64, 3-stage cp.async, 128 threads (4 warps 2x2),
// warp tile 64x64, cross-kt fragment pipelining, 2 CTAs/SM.
// Per-stage mbarrier pipeline (full: cp.async arrive-on, count=128;
// empty: per-warp release arrive, count=4). No mainloop __syncthreads.

#define BM 128
#define BN 128
#define BK 64
#define ROWB 144
#define STAGE_A (BM * ROWB)           // 18432
#define STAGE_B (BN * ROWB)           // 18432
#define STAGE   (STAGE_A + STAGE_B)   // 36864
#define NSTG 3
#define GEMM_SMEM (NSTG * STAGE)      // 110592 (x2 CTAs = 221KB/SM)

__device__ __forceinline__ uint32_t smem_u32(const void* p) {
    uint32_t a;
    asm("{ .reg .u64 t; cvta.to.shared.u64 t, %1; cvt.u32.u64 %0, t; }" : "=r"(a) : "l"(p));
    return a;
}
__device__ __forceinline__ void cp16(uint32_t s, const void* g) {
    asm volatile("cp.async.cg.shared.global [%0], [%1], 16;" :: "r"(s), "l"(g));
}
__device__ __forceinline__ void mbar_init(uint32_t a, uint32_t cnt) {
    asm volatile("mbarrier.init.shared.b64 [%0], %1;" :: "r"(a), "r"(cnt) : "memory");
}
__device__ __forceinline__ void mbar_arrive(uint32_t a) {
    asm volatile("mbarrier.arrive.shared.b64 _, [%0];" :: "r"(a) : "memory");
}
// Route this thread's prior cp.asyncs to the mbarrier (one arrival on completion).
__device__ __forceinline__ void cp_arrive(uint32_t a) {
    asm volatile("cp.async.mbarrier.arrive.noinc.shared.b64 [%0];" :: "r"(a) : "memory");
}
// Block while barrier's current phase parity == p (i.e. wait for phase p done).
__device__ __forceinline__ void mbar_wait(uint32_t a, uint32_t p) {
    uint32_t done;
    asm volatile(
        "{\n\t.reg .pred P;\n\t"
        "mbarrier.try_wait.parity.acquire.cta.shared::cta.b64 P, [%1], %2, 0x989680;\n\t"
        "selp.b32 %0, 1, 0, P;\n\t}"
        : "=r"(done) : "r"(a), "r"(p) : "memory");
    if (!done) {
        asm volatile(
            "{\n\t.reg .pred P;\n\t"
            "WL_%=:\n\t"
            "mbarrier.try_wait.parity.acquire.cta.shared::cta.b64 P, [%0], %1, 0x989680;\n\t"
            "@P bra WD_%=;\n\t"
            "bra WL_%=;\n\t"
            "WD_%=:\n\t}"
            :: "r"(a), "r"(p) : "memory");
    }
}

#define LDSM4(r0, r1, r2, r3, addr) \
    asm volatile("ldmatrix.sync.aligned.m8n8.x4.shared.b16 {%0,%1,%2,%3}, [%4];" \
        : "=r"(r0), "=r"(r1), "=r"(r2), "=r"(r3) : "r"(addr))

__device__ __forceinline__ void mma16816(float* d, const uint32_t* a, const uint32_t* b) {
    asm volatile(
        "mma.sync.aligned.m16n8k16.row.col.f32.f16.f16.f32 "
        "{%0,%1,%2,%3}, {%4,%5,%6,%7}, {%8,%9}, {%0,%1,%2,%3};"
        : "+f"(d[0]), "+f"(d[1]), "+f"(d[2]), "+f"(d[3])
        : "r"(a[0]), "r"(a[1]), "r"(a[2]), "r"(a[3]), "r"(b[0]), "r"(b[1]));
}

// Half-stages for BK=64: 8 cp16/thread each (A: 128x64 fp16, B: 128x64).
__device__ __forceinline__ void issue_stage_A(
    uint32_t sb, int stage, const __half* __restrict__ gA, int kt, int tid, int K)
{
    uint32_t sA = sb + stage * STAGE;
    const __half* ga = gA + (size_t)kt * BK;
    #pragma unroll
    for (int j = 0; j < 8; j++) {
        int cid = tid + j * 128;
        int r = cid >> 3, c = cid & 7;
        cp16(sA + r * ROWB + c * 16, ga + (size_t)r * K + c * 8);
    }
}
__device__ __forceinline__ void issue_stage_B(
    uint32_t sb, int stage, const __half* __restrict__ gB, int kt, int tid, int K)
{
    uint32_t sB = sb + stage * STAGE + STAGE_A;
    const __half* gb = gB + (size_t)kt * BK;
    #pragma unroll
    for (int j = 0; j < 8; j++) {
        int cid = tid + j * 128;
        int r = cid >> 3, c = cid & 7;
        cp16(sB + r * ROWB + c * 16, gb + (size_t)r * K + c * 8);
    }
}

#define LOAD_A_FRAGS(dst, base, kc) do { \
    _Pragma("unroll") \
    for (int mt = 0; mt < 4; mt++) { \
        uint32_t ad = (base) + (aRow + mt * 16) * ROWB + ((aCol + (kc)) * 2); \
        LDSM4((dst)[mt][0], (dst)[mt][1], (dst)[mt][2], (dst)[mt][3], ad); \
    } } while (0)

#define LOAD_B_FRAGS(dst, base, kc) do { \
    _Pragma("unroll") \
    for (int p = 0; p < 4; p++) { \
        uint32_t bd = (base) + (bRowBase + p * 16) * ROWB + ((bCol + (kc)) * 2); \
        uint32_t r0, r1, r2, r3; \
        LDSM4(r0, r1, r2, r3, bd); \
        (dst)[2 * p][0] = r0; (dst)[2 * p][1] = r1; \
        (dst)[2 * p + 1][0] = r2; (dst)[2 * p + 1][1] = r3; \
    } } while (0)

#define MMA_BURST(af, bf) do { \
    _Pragma("unroll") \
    for (int mt = 0; mt < 4; mt++) \
        _Pragma("unroll") \
        for (int nt = 0; nt < 8; nt++) \
            mma16816(acc[mt][nt], (af)[mt], (bf)[nt]); \
    } while (0)

// One kt sub-iteration. ST/ST1/ST2 compile-time stage ids; PE/PF parities;
// PROD: whether stage kt+2 is produced.
#define KT_BODY(KT_IDX, ST, ST1, ST2, PE, PF, PROD) do { \
    uint32_t sA_ = sb + (ST) * STAGE, sB_ = sA_ + STAGE_A; \
    LOAD_A_FRAGS(aF[1], sA_, 16); \
    LOAD_B_FRAGS(bF[1], sB_, 16); \
    MMA_BURST(aF[0], bF[0]);                   /* ks0 */ \
    if (PROD) { \
        mbar_wait(mb_empty[ST2], (PE)); \
        issue_stage_A(sb, (ST2), gA, (KT_IDX) + 2, tid, K); \
    } \
    LOAD_A_FRAGS(aF[0], sA_, 32); \
    LOAD_B_FRAGS(bF[0], sB_, 32); \
    MMA_BURST(aF[1], bF[1]);                   /* ks1 */ \
    if (PROD) { \
        issue_stage_B(sb, (ST2), gB, (KT_IDX) + 2, tid, K); \
        cp_arrive(mb_full[ST2]); \
    } \
    LOAD_A_FRAGS(aF[1], sA_, 48); \
    LOAD_B_FRAGS(bF[1], sB_, 48); \
    if (L == 0) mbar_arrive(mb_empty[ST]);     /* last read of ST done */ \
    MMA_BURST(aF[0], bF[0]);                   /* ks2 */ \
    mbar_wait(mb_full[ST1], (PF)); \
    { uint32_t nA_ = sb + (ST1) * STAGE; \
      LOAD_A_FRAGS(aF[0], nA_, 0); \
      LOAD_B_FRAGS(bF[0], nA_ + STAGE_A, 0); } \
    MMA_BURST(aF[1], bF[1]);                   /* ks3 */ \
    } while (0)

__global__ void __launch_bounds__(128, 2)
gemm_kernel(float* __restrict__ out, const float* __restrict__ bias,
            const __half* __restrict__ A, const __half* __restrict__ B,
            int M, int N, int K)
{
    extern __shared__ char smem[];
    __shared__ uint64_t mbars[6];
    uint32_t sb = smem_u32(smem);
    uint32_t mb_full[3], mb_empty[3];
    #pragma unroll
    for (int s = 0; s < 3; s++) {
        mb_full[s]  = smem_u32(&mbars[s]);
        mb_empty[s] = smem_u32(&mbars[3 + s]);
    }

    int tid = threadIdx.x;
    int wid = tid >> 5, L = tid & 31;
    int warpM = wid >> 1, warpN = wid & 1;         // 2(M) x 2(N)

    int NT = N / BN;                               // 32
    int ntile = blockIdx.x % NT;                   // fast N => W stays L2-hot
    int mtile = blockIdx.x / NT;

    const __half* gA = A + (size_t)(mtile * BM) * K;
    const __half* gB = B + (size_t)(ntile * BN) * K;

    // init barriers; pre-arm empties (phase 0 completes => buffers free)
    if (tid == 0) {
        #pragma unroll
        for (int s = 0; s < 3; s++) {
            mbar_init(mb_full[s], 128);
            mbar_init(mb_empty[s], 4);
        }
        #pragma unroll
        for (int s = 0; s < 3; s++) {
            mbar_arrive(mb_empty[s]); mbar_arrive(mb_empty[s]);
            mbar_arrive(mb_empty[s]); mbar_arrive(mb_empty[s]);
        }
    }
    __syncthreads();                               // barriers visible (only CTA-wide sync)

    float acc[4][8][4];
    #pragma unroll
    for (int i = 0; i < 4; i++)
        #pragma unroll
        for (int j = 0; j < 8; j++)
            #pragma unroll
            for (int q = 0; q < 4; q++) acc[i][j][q] = 0.f;

    // prologue: produce stages 0,1 (full[0] phase0, full[1] phase0)
    issue_stage_A(sb, 0, gA, 0, tid, K);
    issue_stage_B(sb, 0, gB, 0, tid, K);
    cp_arrive(mb_full[0]);
    issue_stage_A(sb, 1, gA, 1, tid, K);
    issue_stage_B(sb, 1, gB, 1, tid, K);
    cp_arrive(mb_full[1]);

    // ldmatrix lane offsets (warp 64x64 mapping validated R6/R11-R16)
    int aRow = warpM * 64 + (L & 15);              // + mt*16
    int aCol = (L >> 4) << 3;                      // + ks*16
    int jb = L >> 3;
    int bRowBase = warpN * 64 + ((jb >> 1) << 3) + (L & 7);   // + p*16
    int bCol = (jb & 1) << 3;                      // + ks*16

    // F0 carries ks0 -> ks2 -> next-ks0 ; F1 carries ks1 -> ks3
    uint32_t aF[2][4][4], bF[2][8][2];

    // consume full[0] phase 0, load kt0 ks0 fragments
    mbar_wait(mb_full[0], 0);
    LOAD_A_FRAGS(aF[0], sb, 0);
    LOAD_B_FRAGS(bF[0], sb + STAGE_A, 0);

    // KT = 64 = 21*3 + 1.
    // Parity schedule (derived; empties pre-armed, full[0]/full[1] prologue):
    //  sub0 (st 0,1,2): PE=j&1 (empty2),      PF=j&1 (full1)
    //  sub1 (st 1,2,0): PE=(j+1)&1 (empty0),  PF=j&1 (full2)
    //  sub2 (st 2,0,1): PE=(j+1)&1 (empty1),  PF=(j+1)&1 (full0)
    for (int j = 0; j < 21; j++) {
        uint32_t p0 = (uint32_t)(j & 1), p1 = p0 ^ 1u;
        int kt0 = 3 * j;
        KT_BODY(kt0,     0, 1, 2, p0, p0, true);
        KT_BODY(kt0 + 1, 1, 2, 0, p1, p0, true);
        KT_BODY(kt0 + 2, 2, 0, 1, p1, p1, (j < 20));
    }

    // peel kt = 63 (stage 0): pure consume, no waits/produces needed
    {
        uint32_t sA_ = sb, sB_ = sb + STAGE_A;
        LOAD_A_FRAGS(aF[1], sA_, 16);
        LOAD_B_FRAGS(bF[1], sB_, 16);
        MMA_BURST(aF[0], bF[0]);                   // ks0
        LOAD_A_FRAGS(aF[0], sA_, 32);
        LOAD_B_FRAGS(bF[0], sB_, 32);
        MMA_BURST(aF[1], bF[1]);                   // ks1
        LOAD_A_FRAGS(aF[1], sA_, 48);
        LOAD_B_FRAGS(bF[1], sB_, 48);
        MMA_BURST(aF[0], bF[0]);                   // ks2
        MMA_BURST(aF[1], bF[1]);                   // ks3
    }

    // ---------------- epilogue: fp32 stores (streaming) + bias ------------
    int rbase = mtile * BM + warpM * 64 + (L >> 2);
    int cbase = ntile * BN + warpN * 64 + (L & 3) * 2;

    float2 bv[8];
    #pragma unroll
    for (int nt = 0; nt < 8; nt++)
        bv[nt] = *(const float2*)(bias + cbase + nt * 8);

    #pragma unroll
    for (int mt = 0; mt < 4; mt++) {
        int r0 = rbase + mt * 16;
        #pragma unroll
        for (int nt = 0; nt < 8; nt++) {
            int c = cbase + nt * 8;
            float2 v0 = { acc[mt][nt][0] + bv[nt].x, acc[mt][nt][1] + bv[nt].y };
            float2 v1 = { acc[mt][nt][2] + bv[nt].x, acc[mt][nt][3] + bv[nt].y };
            __stcs((float2*)(out + (size_t)r0 * N + c), v0);
            __stcs((float2*)(out + (size_t)(r0 + 8) * N + c), v1);
        }
    }
}

// ---------------------------------------------------------------- host -----
extern "C" void kernel_launch(void* const* d_in, const int* in_sizes, int n_in,
                              void* d_out, int out_size)
{
    const float* x    = (const float*)d_in[0];
    const float* w    = (const float*)d_in[1];
    const float* bias = (const float*)d_in[2];
    float* out = (float*)d_out;

    int N  = in_sizes[2];
    int K  = in_sizes[1] / N;
    int M  = in_sizes[0] / K;
    int nw = in_sizes[1];
    int nx = in_sizes[0];

    // Order: gemm stays 4th kernel -> lands in the ncu capture slot.
    xconv_kernel<<<4096, 256>>>(x, nx / 4);
    stats1_kernel<<<1024, 256>>>(w, nw);
    binarize_kernel<<<2048, 256>>>(w, nw / 4, nw);

    void *pXh = nullptr, *pWb = nullptr;
    cudaGetSymbolAddress(&pXh, g_Xh);
    cudaGetSymbolAddress(&pWb, g_Wb);

    cudaFuncSetAttribute(gemm_kernel, cudaFuncAttributeMaxDynamicSharedMemorySize, GEMM_SMEM);

    int grid = (M / BM) * (N / BN);
    gemm_kernel<<<grid, 128, GEMM_SMEM>>>(out, bias, (const __half*)pXh,
                                          (const __half*)pWb, M, N, K);
}